// round 10
// baseline (speedup 1.0000x reference)
#include <cuda_runtime.h>
#include <cstdint>

#define BB 8
#define TT 128
#define DD 512
#define OO 512
#define CPG 8              // CTAs per cluster (one cluster per batch)
#define OSL (OO/CPG)       // 64  output-col slice per CTA
#define NTH 256
#define FULLMASK 0xffffffffu

// ---------------- device scratch (no allocations allowed) ----------------
__device__ float g_UaH[BB*TT*OO];   // inputs@Ua + Ba
__device__ float g_IC [BB*TT*OO];   // inputs@Co
__device__ float g_XUo[BB*TT*OO];   // inputs@Uo
__device__ float g_embWo[OO];       // emb@Wo

// ---------------- helpers ----------------
__device__ __forceinline__ float wredsum(float v) {
    #pragma unroll
    for (int s = 16; s; s >>= 1) v += __shfl_xor_sync(FULLMASK, v, s);
    return v;
}
__device__ __forceinline__ float tanhapx(float x) {
    float y;
    asm("tanh.approx.f32 %0, %1;" : "=f"(y) : "f"(x));
    return y;
}
__device__ __forceinline__ uint32_t smem_u32(const void* p) {
    uint32_t a;
    asm("{ .reg .u64 t; cvta.to.shared.u64 t, %1; cvt.u32.u64 %0, t; }"
        : "=r"(a) : "l"(p));
    return a;
}
__device__ __forceinline__ uint32_t dsm_map(uint32_t laddr, uint32_t rank) {
    uint32_t r;
    asm("mapa.shared::cluster.u32 %0, %1, %2;" : "=r"(r) : "r"(laddr), "r"(rank));
    return r;
}
__device__ __forceinline__ void mbar_init(uint32_t a, uint32_t cnt) {
    asm volatile("mbarrier.init.shared.b64 [%0], %1;" :: "r"(a), "r"(cnt) : "memory");
}
__device__ __forceinline__ void mbar_arm(uint32_t a, uint32_t tx) {
    asm volatile("mbarrier.arrive.expect_tx.shared.b64 _, [%0], %1;"
                 :: "r"(a), "r"(tx) : "memory");
}
__device__ __forceinline__ void mbar_wait(uint32_t a, uint32_t parity) {
    asm volatile(
        "{\n\t.reg .pred P;\n\t"
        "W_%=:\n\t"
        "mbarrier.try_wait.parity.acquire.cluster.shared::cta.b64 P, [%0], %1, 0x989680;\n\t"
        "@!P bra W_%=;\n\t}"
        :: "r"(a), "r"(parity) : "memory");
}
// fire-and-forget remote store, completion counted on remote mbarrier (bytes)
__device__ __forceinline__ void st_async(uint32_t raddr, float v, uint32_t rbar) {
    asm volatile(
        "st.async.shared::cluster.mbarrier::complete_tx::bytes.b32 [%0], %1, [%2];"
        :: "r"(raddr), "r"(__float_as_uint(v)), "r"(rbar) : "memory");
}
#define CLUSTER_SYNC() do { \
    asm volatile("barrier.cluster.arrive.aligned;" ::: "memory"); \
    asm volatile("barrier.cluster.wait.aligned;"   ::: "memory"); \
} while (0)

// packed fp32x2 fma (register/broadcast-LDS operands only; NOT in GEMM)
__device__ __forceinline__ void fma2(unsigned long long& d,
                                     unsigned long long a, unsigned long long b) {
    asm("fma.rn.f32x2 %0, %1, %2, %0;" : "+l"(d) : "l"(a), "l"(b));
}
__device__ __forceinline__ unsigned long long pack2(float x, float y) {
    unsigned long long r;
    asm("mov.b64 %0, {%1, %2};" : "=l"(r) : "f"(x), "f"(y));
    return r;
}
__device__ __forceinline__ float2 unpack2(unsigned long long v) {
    float2 r;
    asm("mov.b64 {%0, %1}, %2;" : "=f"(r.x), "=f"(r.y) : "l"(v));
    return r;
}

// =======================================================================
// GEMM (known-good, 58.4us): C_z = A[1024x512] @ B_z[512x512]
// 64x64 tile, BK=16, 256 threads, 4x4/thread, register prefetch.
// =======================================================================
__global__ __launch_bounds__(256) void gemm3_kernel(
    const float* __restrict__ A,
    const float* __restrict__ Ua,
    const float* __restrict__ Co,
    const float* __restrict__ Uo,
    const float* __restrict__ Ba)
{
    __shared__ float As[16][64];   // k-major
    __shared__ float Bs[16][64];

    const int m0 = blockIdx.x * 64;
    const int n0 = blockIdx.y * 64;
    const int z  = blockIdx.z;
    const float* __restrict__ Bm = (z == 0) ? Ua : ((z == 1) ? Co : Uo);
    float* Cout = (z == 0) ? g_UaH : ((z == 1) ? g_IC : g_XUo);

    const int tid  = threadIdx.x;
    const int tx   = tid & 15;
    const int ty   = tid >> 4;
    const int la_m = tid >> 2;
    const int la_k = (tid & 3) << 2;
    const int lb_k = tid >> 4;
    const int lb_n = (tid & 15) << 2;

    float acc[4][4];
    #pragma unroll
    for (int i = 0; i < 4; i++)
        #pragma unroll
        for (int j = 0; j < 4; j++) acc[i][j] = 0.f;

    float4 av = *(const float4*)&A [(m0 + la_m) * DD + la_k];
    float4 bv = *(const float4*)&Bm[lb_k * OO + n0 + lb_n];

    for (int k0 = 0; k0 < DD; k0 += 16) {
        __syncthreads();
        As[la_k + 0][la_m] = av.x;
        As[la_k + 1][la_m] = av.y;
        As[la_k + 2][la_m] = av.z;
        As[la_k + 3][la_m] = av.w;
        *(float4*)&Bs[lb_k][lb_n] = bv;
        __syncthreads();
        if (k0 + 16 < DD) {
            av = *(const float4*)&A [(m0 + la_m) * DD + (k0 + 16) + la_k];
            bv = *(const float4*)&Bm[(k0 + 16 + lb_k) * OO + n0 + lb_n];
        }
        #pragma unroll
        for (int kk = 0; kk < 16; kk++) {
            float4 a = *(const float4*)&As[kk][ty << 2];
            float4 b = *(const float4*)&Bs[kk][tx << 2];
            acc[0][0] += a.x * b.x; acc[0][1] += a.x * b.y; acc[0][2] += a.x * b.z; acc[0][3] += a.x * b.w;
            acc[1][0] += a.y * b.x; acc[1][1] += a.y * b.y; acc[1][2] += a.y * b.z; acc[1][3] += a.y * b.w;
            acc[2][0] += a.z * b.x; acc[2][1] += a.z * b.y; acc[2][2] += a.z * b.z; acc[2][3] += a.z * b.w;
            acc[3][0] += a.w * b.x; acc[3][1] += a.w * b.y; acc[3][2] += a.w * b.z; acc[3][3] += a.w * b.w;
        }
    }
    #pragma unroll
    for (int i = 0; i < 4; i++) {
        int r = m0 + (ty << 2) + i;
        #pragma unroll
        for (int j = 0; j < 4; j++) {
            int c = n0 + (tx << 2) + j;
            float v = acc[i][j];
            if (z == 0) v += Ba[c];
            Cout[(size_t)r * OO + c] = v;
        }
    }
}

// =======================================================================
// embWo[i] = sum_j emb[i][j] * Wo[j]
// =======================================================================
__global__ __launch_bounds__(256) void embwo_kernel(
    const float* __restrict__ emb, const float* __restrict__ Wo)
{
    const int row  = (blockIdx.x << 3) + (threadIdx.x >> 5);
    const int lane = threadIdx.x & 31;
    const float* rp = emb + row * OO;
    float acc = 0.f;
    #pragma unroll 4
    for (int j = lane; j < OO; j += 32) acc += rp[j] * Wo[j];
    acc = wredsum(acc);
    if (lane == 0) g_embWo[row] = acc;
}

// =======================================================================
// Persistent clustered scan. Changes vs R9 (all on the inter-CTA chain):
//  - sender ships ONLY sig; receivers reconstruct e = sig/(1-sig) and do
//    the S/P reductions in the score-wait shadow (260 cyc off chain)
//  - WaS: quad-shuffle reduce, 4 accumulators (no smem round trip)
//  - 2-acc ILP in P2 / score-sum / ctx
// =======================================================================
#define UAH_PITCH 76
#define SG_PITCH  68        // 64 sig per rank (272B rows, 16B aligned)
// shared memory layout (float offsets)
#define UAH_OFF   0                              // [128][76] = 9728
#define IC_OFF    (UAH_OFF + TT*UAH_PITCH)       // [128][64] = 8192
#define SG_OFF    (IC_OFF + TT*OSL)              // 2 x [8][68] = 1088
#define SPART_OFF (SG_OFF + 2*CPG*SG_PITCH)      // 2 x [8][128] = 2048
#define WAS_OFF   (SPART_OFF + 2*CPG*TT)         // [64]
#define WBUF_OFF  (WAS_OFF + OSL)                // [128]
#define RED_OFF   (WBUF_OFF + TT)                // [32]
#define PART_OFF  (RED_OFF + 32)                 // [256]
#define BAR_OFF   (PART_OFF + 256)               // 4 x u64 (score0,score1,sig0,sig1)
#define SMEM_FLOATS (BAR_OFF + 8)
#define SMEM_BYTES  (SMEM_FLOATS * 4)

#define TX_SCORE (CPG*TT*4)          // 4096 bytes/phase
#define TX_SIG   (CPG*OSL*4)         // 2048 bytes/phase (sig only)

__global__ __launch_bounds__(NTH, 1) __cluster_dims__(CPG, 1, 1)
void scan_kernel(const float* __restrict__ Wa,
                 const float* __restrict__ Va,
                 const float* __restrict__ Bo,
                 float* __restrict__ out)
{
    extern __shared__ float sm[];
    float* UaH_s = sm + UAH_OFF;
    float* IC_s  = sm + IC_OFF;
    float* wbuf  = sm + WBUF_OFF;
    float* WaS_s = sm + WAS_OFF;
    float* red   = sm + RED_OFF;
    float* partB = sm + PART_OFF;

    const uint32_t sbase   = smem_u32(sm);
    const uint32_t barbase = sbase + BAR_OFF * 4;

    const int tid  = threadIdx.x;
    const int lane = tid & 31;
    const int wid  = tid >> 5;
    const int b    = blockIdx.x >> 3;     // batch
    const int crk  = blockIdx.x & 7;      // cluster rank
    const int o_base = crk * OSL;
    const int oc   = tid & 63;            // P3 ctx split
    const int kc   = tid >> 6;            // P3 ctx split (0..3)
    const int ts   = tid & 127;           // P2 timestep
    const int q    = tid >> 7;            // P2 o-half
    const int col4 = tid >> 2;            // WaS col (0..63)
    const int kq   = tid & 3;             // WaS k-quarter

    // ---------------- prologue ----------------
    for (int i = tid; i < TT * OSL; i += NTH) {
        int tt = i >> 6, o = i & 63;
        UaH_s[tt * UAH_PITCH + o] = g_UaH[(size_t)(b * TT + tt) * OO + o_base + o];
        IC_s[(tt << 6) + o]       = g_IC [(size_t)(b * TT + tt) * OO + o_base + o];
    }

    // Wa slice packed: thread (col4,kq) holds k in [kq*128, kq*128+128)
    unsigned long long wreg2[64];
    {
        const int colg = o_base + col4;
        #pragma unroll
        for (int m = 0; m < 64; m++) {
            float w0 = Wa[(size_t)(kq * 128 + 2 * m)     * OO + colg];
            float w1 = Wa[(size_t)(kq * 128 + 2 * m + 1) * OO + colg];
            wreg2[m] = pack2(w0, w1);
        }
    }
    float va_r[32];
    #pragma unroll
    for (int j = 0; j < 32; j++) va_r[j] = Va[o_base + (q << 5) + j];

    const float ew0  = g_embWo[tid];
    const float ew1  = g_embWo[tid + 256];
    const float bo_r = (tid < OSL) ? Bo[o_base + tid] : 0.f;

    uint32_t rbase[CPG];
    #pragma unroll
    for (int r = 0; r < CPG; r++) rbase[r] = dsm_map(sbase, r);

    if (tid == 0) {
        #pragma unroll
        for (int i = 0; i < 4; i++) mbar_init(barbase + i * 8, 1);
        mbar_arm(barbase + 0,  TX_SCORE);
        mbar_arm(barbase + 8,  TX_SCORE);
        mbar_arm(barbase + 16, TX_SIG);
        mbar_arm(barbase + 24, TX_SIG);
    }

    // t=0 seed: sig(-1)=0.5 in sg buffer 1 -> e=1 -> S=512, P=sum(embWo) auto
    {
        float* sg1 = sm + SG_OFF + CPG * SG_PITCH;
        for (int i = tid; i < CPG * SG_PITCH; i += NTH)
            sg1[i] = ((i % SG_PITCH) < OSL) ? 0.5f : 0.f;
    }
    __syncthreads();
    CLUSTER_SYNC();   // barriers initialized+armed everywhere before any st.async

    // ---------------- scan over T steps ----------------
    for (int t = 0; t < TT; t++) {
        const int buf = t & 1;

        float xo = 0.f;
        if (tid < OSL)
            xo = __ldg(&g_XUo[(size_t)(b * TT + ((t + TT - 1) & (TT - 1))) * OO + o_base + tid]);

        // -------- wait for sig of pred(t-1) --------
        const uint32_t sigbar_l = barbase + 16 + (buf ^ 1) * 8;
        if (t > 0) {
            mbar_wait(sigbar_l, ((t - 1) >> 1) & 1);
            if (tid == 0) mbar_arm(sigbar_l, TX_SIG);
        }
        const float* sgc = sm + SG_OFF + (buf ^ 1) * (CPG * SG_PITCH);

        // -------- WaS (fp32x2, 4 accs, quad-shuffle reduce) --------
        {
            unsigned long long a0 = 0ull, a1 = 0ull, a2 = 0ull, a3 = 0ull;
            const ulonglong2* r0 = (const ulonglong2*)(sgc + (2 * kq)     * SG_PITCH);
            const ulonglong2* r1 = (const ulonglong2*)(sgc + (2 * kq + 1) * SG_PITCH);
            #pragma unroll
            for (int i = 0; i < 16; i++) {
                ulonglong2 sv = r0[i];
                fma2(a0, sv.x, wreg2[2 * i]);
                fma2(a1, sv.y, wreg2[2 * i + 1]);
            }
            #pragma unroll
            for (int i = 0; i < 16; i++) {
                ulonglong2 sv = r1[i];
                fma2(a2, sv.x, wreg2[32 + 2 * i]);
                fma2(a3, sv.y, wreg2[32 + 2 * i + 1]);
            }
            float2 f0 = unpack2(a0), f1 = unpack2(a1);
            float2 f2 = unpack2(a2), f3 = unpack2(a3);
            float w = ((f0.x + f0.y) + (f1.x + f1.y))
                    + ((f2.x + f2.y) + (f3.x + f3.y));
            w += __shfl_xor_sync(FULLMASK, w, 1);
            w += __shfl_xor_sync(FULLMASK, w, 2);
            if (kq == 0) WaS_s[col4] = w;
        }
        __syncthreads();                                   // s1: WaS_s ready

        // -------- P2: partial scores, all t, own o-half (2 accs) --------
        {
            const float* urow = UaH_s + ts * UAH_PITCH + (q << 5);
            const float* wp   = WaS_s + (q << 5);
            float acc0 = 0.f, acc1 = 0.f;
            #pragma unroll
            for (int j = 0; j < 8; j++) {
                float4 u = *(const float4*)&urow[j << 2];
                float4 w = *(const float4*)&wp[j << 2];
                acc0 += tanhapx(u.x + w.x) * va_r[(j << 2) + 0]
                      + tanhapx(u.y + w.y) * va_r[(j << 2) + 1];
                acc1 += tanhapx(u.z + w.z) * va_r[(j << 2) + 2]
                      + tanhapx(u.w + w.w) * va_r[(j << 2) + 3];
            }
            partB[(q << 7) + ts] = acc0 + acc1;
        }
        __syncthreads();                                   // s2
        if (tid < TT) {
            float s = partB[tid] + partB[128 + tid];
            const uint32_t doff = (uint32_t)(SPART_OFF + buf * (CPG * TT) + crk * TT + tid) * 4u;
            const uint32_t boff = (uint32_t)(BAR_OFF * 4 + buf * 8);
            #pragma unroll
            for (int r = 0; r < CPG; r++)
                st_async(rbase[r] + doff, s, rbase[r] + boff);
        }

        // -------- S/P reductions in the score-wait shadow --------
        // e^pred = sig/(1-sig); embWo order matches global o index.
        {
            float sg0 = sgc[(tid >> 6) * SG_PITCH + (tid & 63)];
            int v1 = tid + 256;
            float sg1 = sgc[(v1 >> 6) * SG_PITCH + (v1 & 63)];
            float e0 = __fdividef(sg0, 1.f - sg0);
            float e1 = __fdividef(sg1, 1.f - sg1);
            float ps = wredsum(e0 + e1);
            float pd = wredsum(e0 * ew0 + e1 * ew1);
            if (lane == 0) { red[8 + wid] = ps; red[16 + wid] = pd; }
        }

        // -------- wait for all score partials --------
        const uint32_t scorebar_l = barbase + buf * 8;
        mbar_wait(scorebar_l, (t >> 1) & 1);
        if (tid == 0) mbar_arm(scorebar_l, TX_SCORE);

        // -------- P3: softmax over T + ctx + pred + sig broadcast --------
        const float* sp = sm + SPART_OFF + buf * (CPG * TT);
        if (tid < TT) {
            float c0 = 0.f, c1 = 0.f;
            #pragma unroll
            for (int r = 0; r < 8; r += 2) {
                c0 += sp[(r << 7) + tid];
                c1 += sp[((r + 1) << 7) + tid];
            }
            float esv = __expf(c0 + c1);                   // |score| small: no max-sub
            wbuf[tid] = esv;
            float spp = wredsum(esv);
            if (lane == 0) red[wid] = spp;                 // wid 0..3
        }
        __syncthreads();                                   // s3: wbuf + red (esum,S,P)
        const float esum = (red[0] + red[1]) + (red[2] + red[3]);

        // ctx partial: thread (oc,kc) covers t' in [kc*32, kc*32+32), 2 accs
        {
            float c0 = 0.f, c1 = 0.f;
            const int base = kc << 5;
            #pragma unroll
            for (int j = 0; j < 8; j++) {
                float4 wb = *(const float4*)&wbuf[base + (j << 2)];
                c0 += wb.x * IC_s[((base + (j << 2) + 0) << 6) + oc]
                    + wb.y * IC_s[((base + (j << 2) + 1) << 6) + oc];
                c1 += wb.z * IC_s[((base + (j << 2) + 2) << 6) + oc]
                    + wb.w * IC_s[((base + (j << 2) + 3) << 6) + oc];
            }
            partB[tid] = c0 + c1;
        }
        __syncthreads();                                   // s4
        if (tid < OSL) {
            float S = ((red[8]  + red[9])  + (red[10] + red[11]))
                    + ((red[12] + red[13]) + (red[14] + red[15]));
            float P = ((red[16] + red[17]) + (red[18] + red[19]))
                    + ((red[20] + red[21]) + (red[22] + red[23]));
            const float woy = __fdividef(P, S);
            float ctx  = (partB[tid] + partB[64 + tid]) + (partB[128 + tid] + partB[192 + tid]);
            float pred = woy + xo + __fdividef(ctx, esum) + bo_r;

            // ship sig FIRST (inter-step critical path), then store out
            float sg = __fdividef(1.f, 1.f + __expf(-pred));
            if (t < TT - 1) {
                const uint32_t sgoff =
                    (uint32_t)(SG_OFF + buf * (CPG * SG_PITCH) + crk * SG_PITCH + tid) * 4u;
                const uint32_t sboff = (uint32_t)(BAR_OFF * 4 + 16 + buf * 8);
                #pragma unroll
                for (int r = 0; r < CPG; r++)
                    st_async(rbase[r] + sgoff, sg, rbase[r] + sboff);
            }
            out[(size_t)(b * TT + t) * OO + o_base + tid] = pred;
        }
    }
    CLUSTER_SYNC();   // no CTA exits while peers' in-flight stores may target it
}

// =======================================================================
// launch
// =======================================================================
extern "C" void kernel_launch(void* const* d_in, const int* in_sizes, int n_in,
                              void* d_out, int out_size)
{
    const float* inputs = (const float*)d_in[0];
    const float* Wa     = (const float*)d_in[1];
    const float* Ua     = (const float*)d_in[2];
    const float* Va     = (const float*)d_in[3];
    const float* Ba     = (const float*)d_in[4];
    const float* Wo     = (const float*)d_in[5];
    const float* Uo     = (const float*)d_in[6];
    const float* Co     = (const float*)d_in[7];
    const float* Bo     = (const float*)d_in[8];
    const float* emb    = (const float*)d_in[9];
    float* out = (float*)d_out;

    dim3 g(16, 8, 3);
    gemm3_kernel<<<g, 256>>>(inputs, Ua, Co, Uo, Ba);
    embwo_kernel<<<64, 256>>>(emb, Wo);

    cudaFuncSetAttribute(scan_kernel,
                         cudaFuncAttributeMaxDynamicSharedMemorySize, SMEM_BYTES);
    scan_kernel<<<BB * CPG, NTH, SMEM_BYTES>>>(Wa, Va, Bo, out);
}

// round 11
// speedup vs baseline: 1.0139x; 1.0139x over previous
#include <cuda_runtime.h>
#include <cstdint>

#define BB 8
#define TT 128
#define DD 512
#define OO 512
#define CPG 8              // CTAs per cluster (one cluster per batch)
#define OSL (OO/CPG)       // 64  output-col slice per CTA
#define NTH 256
#define FULLMASK 0xffffffffu

// ---------------- device scratch (no allocations allowed) ----------------
__device__ float g_UaH[BB*TT*OO];   // inputs@Ua + Ba
__device__ float g_IC [BB*TT*OO];   // inputs@Co
__device__ float g_XUo[BB*TT*OO];   // inputs@Uo
__device__ float g_embWo[OO];       // emb@Wo

// ---------------- helpers ----------------
__device__ __forceinline__ float wredsum(float v) {
    #pragma unroll
    for (int s = 16; s; s >>= 1) v += __shfl_xor_sync(FULLMASK, v, s);
    return v;
}
__device__ __forceinline__ float tanhapx(float x) {
    float y;
    asm("tanh.approx.f32 %0, %1;" : "=f"(y) : "f"(x));
    return y;
}
__device__ __forceinline__ uint32_t smem_u32(const void* p) {
    uint32_t a;
    asm("{ .reg .u64 t; cvta.to.shared.u64 t, %1; cvt.u32.u64 %0, t; }"
        : "=r"(a) : "l"(p));
    return a;
}
__device__ __forceinline__ uint32_t dsm_map(uint32_t laddr, uint32_t rank) {
    uint32_t r;
    asm("mapa.shared::cluster.u32 %0, %1, %2;" : "=r"(r) : "r"(laddr), "r"(rank));
    return r;
}
__device__ __forceinline__ void mbar_init(uint32_t a, uint32_t cnt) {
    asm volatile("mbarrier.init.shared.b64 [%0], %1;" :: "r"(a), "r"(cnt) : "memory");
}
__device__ __forceinline__ void mbar_arm(uint32_t a, uint32_t tx) {
    asm volatile("mbarrier.arrive.expect_tx.shared.b64 _, [%0], %1;"
                 :: "r"(a), "r"(tx) : "memory");
}
__device__ __forceinline__ void mbar_wait(uint32_t a, uint32_t parity) {
    asm volatile(
        "{\n\t.reg .pred P;\n\t"
        "W_%=:\n\t"
        "mbarrier.try_wait.parity.acquire.cluster.shared::cta.b64 P, [%0], %1, 0x989680;\n\t"
        "@!P bra W_%=;\n\t}"
        :: "r"(a), "r"(parity) : "memory");
}
// fire-and-forget remote store, completion counted on remote mbarrier (bytes)
__device__ __forceinline__ void st_async(uint32_t raddr, float v, uint32_t rbar) {
    asm volatile(
        "st.async.shared::cluster.mbarrier::complete_tx::bytes.b32 [%0], %1, [%2];"
        :: "r"(raddr), "r"(__float_as_uint(v)), "r"(rbar) : "memory");
}
#define CLUSTER_SYNC() do { \
    asm volatile("barrier.cluster.arrive.aligned;" ::: "memory"); \
    asm volatile("barrier.cluster.wait.aligned;"   ::: "memory"); \
} while (0)

// packed fp32x2 fma (register/broadcast-LDS operands only; NOT in GEMM)
__device__ __forceinline__ void fma2(unsigned long long& d,
                                     unsigned long long a, unsigned long long b) {
    asm("fma.rn.f32x2 %0, %1, %2, %0;" : "+l"(d) : "l"(a), "l"(b));
}
__device__ __forceinline__ unsigned long long pack2(float x, float y) {
    unsigned long long r;
    asm("mov.b64 %0, {%1, %2};" : "=l"(r) : "f"(x), "f"(y));
    return r;
}
__device__ __forceinline__ float2 unpack2(unsigned long long v) {
    float2 r;
    asm("mov.b64 {%0, %1}, %2;" : "=f"(r.x), "=f"(r.y) : "l"(v));
    return r;
}

// =======================================================================
// GEMM (known-good, 58.4us): C_z = A[1024x512] @ B_z[512x512]
// 64x64 tile, BK=16, 256 threads, 4x4/thread, register prefetch.
// =======================================================================
__global__ __launch_bounds__(256) void gemm3_kernel(
    const float* __restrict__ A,
    const float* __restrict__ Ua,
    const float* __restrict__ Co,
    const float* __restrict__ Uo,
    const float* __restrict__ Ba)
{
    __shared__ float As[16][64];   // k-major
    __shared__ float Bs[16][64];

    const int m0 = blockIdx.x * 64;
    const int n0 = blockIdx.y * 64;
    const int z  = blockIdx.z;
    const float* __restrict__ Bm = (z == 0) ? Ua : ((z == 1) ? Co : Uo);
    float* Cout = (z == 0) ? g_UaH : ((z == 1) ? g_IC : g_XUo);

    const int tid  = threadIdx.x;
    const int tx   = tid & 15;
    const int ty   = tid >> 4;
    const int la_m = tid >> 2;
    const int la_k = (tid & 3) << 2;
    const int lb_k = tid >> 4;
    const int lb_n = (tid & 15) << 2;

    float acc[4][4];
    #pragma unroll
    for (int i = 0; i < 4; i++)
        #pragma unroll
        for (int j = 0; j < 4; j++) acc[i][j] = 0.f;

    float4 av = *(const float4*)&A [(m0 + la_m) * DD + la_k];
    float4 bv = *(const float4*)&Bm[lb_k * OO + n0 + lb_n];

    for (int k0 = 0; k0 < DD; k0 += 16) {
        __syncthreads();
        As[la_k + 0][la_m] = av.x;
        As[la_k + 1][la_m] = av.y;
        As[la_k + 2][la_m] = av.z;
        As[la_k + 3][la_m] = av.w;
        *(float4*)&Bs[lb_k][lb_n] = bv;
        __syncthreads();
        if (k0 + 16 < DD) {
            av = *(const float4*)&A [(m0 + la_m) * DD + (k0 + 16) + la_k];
            bv = *(const float4*)&Bm[(k0 + 16 + lb_k) * OO + n0 + lb_n];
        }
        #pragma unroll
        for (int kk = 0; kk < 16; kk++) {
            float4 a = *(const float4*)&As[kk][ty << 2];
            float4 b = *(const float4*)&Bs[kk][tx << 2];
            acc[0][0] += a.x * b.x; acc[0][1] += a.x * b.y; acc[0][2] += a.x * b.z; acc[0][3] += a.x * b.w;
            acc[1][0] += a.y * b.x; acc[1][1] += a.y * b.y; acc[1][2] += a.y * b.z; acc[1][3] += a.y * b.w;
            acc[2][0] += a.z * b.x; acc[2][1] += a.z * b.y; acc[2][2] += a.z * b.z; acc[2][3] += a.z * b.w;
            acc[3][0] += a.w * b.x; acc[3][1] += a.w * b.y; acc[3][2] += a.w * b.z; acc[3][3] += a.w * b.w;
        }
    }
    #pragma unroll
    for (int i = 0; i < 4; i++) {
        int r = m0 + (ty << 2) + i;
        #pragma unroll
        for (int j = 0; j < 4; j++) {
            int c = n0 + (tx << 2) + j;
            float v = acc[i][j];
            if (z == 0) v += Ba[c];
            Cout[(size_t)r * OO + c] = v;
        }
    }
}

// =======================================================================
// embWo[i] = sum_j emb[i][j] * Wo[j]
// =======================================================================
__global__ __launch_bounds__(256) void embwo_kernel(
    const float* __restrict__ emb, const float* __restrict__ Wo)
{
    const int row  = (blockIdx.x << 3) + (threadIdx.x >> 5);
    const int lane = threadIdx.x & 31;
    const float* rp = emb + row * OO;
    float acc = 0.f;
    #pragma unroll 4
    for (int j = lane; j < OO; j += 32) acc += rp[j] * Wo[j];
    acc = wredsum(acc);
    if (lane == 0) g_embWo[row] = acc;
}

// =======================================================================
// Persistent clustered scan, warp-specialized:
//  - warps 0-3: P2 full-o score per timestep, send immediately (no s2/partB)
//  - warps 4-7: S/P (woy numerator/denominator) locally from received sig,
//               truly in parallel with P2 (e = sig/(1-sig))
//  - tail: pred -> sig -> 8 sends -> STG (no reductions on the chain)
//  - WaS: fp32x2 + quad-shuffle (no smem round trip)
// =======================================================================
#define UAH_PITCH 76
#define SG_PITCH  68
// shared memory layout (float offsets; 16B aligned)
#define UAH_OFF   0                              // [128][76] = 9728
#define IC_OFF    (UAH_OFF + TT*UAH_PITCH)       // [128][64] = 8192
#define SG_OFF    (IC_OFF + TT*OSL)              // 2 x [8][68] = 1088
#define SPART_OFF (SG_OFF + 2*CPG*SG_PITCH)      // 2 x [8][128] = 2048
#define WAS_OFF   (SPART_OFF + 2*CPG*TT)         // [64]
#define WBUF_OFF  (WAS_OFF + OSL)                // [128]
#define EW_OFF    (WBUF_OFF + TT)                // [512] embWo staged
#define VA_OFF    (EW_OFF + OO)                  // [64]  Va slice staged
#define RED_OFF   (VA_OFF + OSL)                 // [32]
#define PART_OFF  (RED_OFF + 32)                 // [256] (P3 ctx partials)
#define BAR_OFF   (PART_OFF + 256)               // 4 x u64 (score0,score1,sig0,sig1)
#define SMEM_FLOATS (BAR_OFF + 8)
#define SMEM_BYTES  (SMEM_FLOATS * 4)

#define TX_SCORE (CPG*TT*4)          // 4096 bytes/phase
#define TX_SIG   (CPG*OSL*4)         // 2048 bytes/phase (sig only)

__global__ __launch_bounds__(NTH, 1) __cluster_dims__(CPG, 1, 1)
void scan_kernel(const float* __restrict__ Wa,
                 const float* __restrict__ Va,
                 const float* __restrict__ Bo,
                 float* __restrict__ out)
{
    extern __shared__ float sm[];
    float* UaH_s = sm + UAH_OFF;
    float* IC_s  = sm + IC_OFF;
    float* wbuf  = sm + WBUF_OFF;
    float* WaS_s = sm + WAS_OFF;
    float* ew_s  = sm + EW_OFF;
    float* va_s  = sm + VA_OFF;
    float* red   = sm + RED_OFF;
    float* partB = sm + PART_OFF;

    const uint32_t sbase   = smem_u32(sm);
    const uint32_t barbase = sbase + BAR_OFF * 4;

    const int tid  = threadIdx.x;
    const int lane = tid & 31;
    const int wid  = tid >> 5;
    const int b    = blockIdx.x >> 3;     // batch
    const int crk  = blockIdx.x & 7;      // cluster rank
    const int o_base = crk * OSL;
    const int oc   = tid & 63;            // P3 ctx split
    const int kc   = tid >> 6;            // P3 ctx split (0..3)
    const int col4 = tid >> 2;            // WaS col (0..63)
    const int kq   = tid & 3;             // WaS k-quarter

    // ---------------- prologue ----------------
    for (int i = tid; i < TT * OSL; i += NTH) {
        int tt = i >> 6, o = i & 63;
        UaH_s[tt * UAH_PITCH + o] = g_UaH[(size_t)(b * TT + tt) * OO + o_base + o];
        IC_s[(tt << 6) + o]       = g_IC [(size_t)(b * TT + tt) * OO + o_base + o];
    }
    for (int i = tid; i < OO; i += NTH) ew_s[i] = g_embWo[i];
    if (tid < OSL) va_s[tid] = Va[o_base + tid];

    // Wa slice packed: thread (col4,kq) holds k in [kq*128, kq*128+128)
    unsigned long long wreg2[64];
    {
        const int colg = o_base + col4;
        #pragma unroll
        for (int m = 0; m < 64; m++) {
            float w0 = Wa[(size_t)(kq * 128 + 2 * m)     * OO + colg];
            float w1 = Wa[(size_t)(kq * 128 + 2 * m + 1) * OO + colg];
            wreg2[m] = pack2(w0, w1);
        }
    }
    const float bo_r = (tid < OSL) ? Bo[o_base + tid] : 0.f;

    uint32_t rbase[CPG];
    #pragma unroll
    for (int r = 0; r < CPG; r++) rbase[r] = dsm_map(sbase, r);

    if (tid == 0) {
        #pragma unroll
        for (int i = 0; i < 4; i++) mbar_init(barbase + i * 8, 1);
        mbar_arm(barbase + 0,  TX_SCORE);
        mbar_arm(barbase + 8,  TX_SCORE);
        mbar_arm(barbase + 16, TX_SIG);
        mbar_arm(barbase + 24, TX_SIG);
    }

    // t=0 seed: sig(-1)=0.5 in sg buffer 1 -> e=1 -> S=512, P=sum(embWo)
    {
        float* sg1 = sm + SG_OFF + CPG * SG_PITCH;
        for (int i = tid; i < CPG * SG_PITCH; i += NTH)
            sg1[i] = ((i % SG_PITCH) < OSL) ? 0.5f : 0.f;
    }
    __syncthreads();
    CLUSTER_SYNC();   // barriers initialized+armed everywhere before any st.async

    // ---------------- scan over T steps ----------------
    for (int t = 0; t < TT; t++) {
        const int buf = t & 1;

        float xo = 0.f;
        if (tid < OSL)
            xo = __ldg(&g_XUo[(size_t)(b * TT + ((t + TT - 1) & (TT - 1))) * OO + o_base + tid]);

        // -------- wait for sig of pred(t-1) --------
        const uint32_t sigbar_l = barbase + 16 + (buf ^ 1) * 8;
        if (t > 0) {
            mbar_wait(sigbar_l, ((t - 1) >> 1) & 1);
            if (tid == 0) mbar_arm(sigbar_l, TX_SIG);
        }
        const float* sgc = sm + SG_OFF + (buf ^ 1) * (CPG * SG_PITCH);

        // -------- WaS (fp32x2, 4 accs, quad-shuffle reduce) --------
        {
            unsigned long long a0 = 0ull, a1 = 0ull, a2 = 0ull, a3 = 0ull;
            const ulonglong2* r0 = (const ulonglong2*)(sgc + (2 * kq)     * SG_PITCH);
            const ulonglong2* r1 = (const ulonglong2*)(sgc + (2 * kq + 1) * SG_PITCH);
            #pragma unroll
            for (int i = 0; i < 16; i++) {
                ulonglong2 sv = r0[i];
                fma2(a0, sv.x, wreg2[2 * i]);
                fma2(a1, sv.y, wreg2[2 * i + 1]);
            }
            #pragma unroll
            for (int i = 0; i < 16; i++) {
                ulonglong2 sv = r1[i];
                fma2(a2, sv.x, wreg2[32 + 2 * i]);
                fma2(a3, sv.y, wreg2[32 + 2 * i + 1]);
            }
            float2 f0 = unpack2(a0), f1 = unpack2(a1);
            float2 f2 = unpack2(a2), f3 = unpack2(a3);
            float w = ((f0.x + f0.y) + (f1.x + f1.y))
                    + ((f2.x + f2.y) + (f3.x + f3.y));
            w += __shfl_xor_sync(FULLMASK, w, 1);
            w += __shfl_xor_sync(FULLMASK, w, 2);
            if (kq == 0) WaS_s[col4] = w;
        }
        __syncthreads();                                   // s1: WaS_s ready

        if (tid < TT) {
            // -------- warps 0-3: full-o score for own timestep + send --------
            const float* urow = UaH_s + tid * UAH_PITCH;
            float a0 = 0.f, a1 = 0.f;
            #pragma unroll
            for (int j = 0; j < 16; j++) {
                float4 u = *(const float4*)&urow[j << 2];   // lane-specific
                float4 w = *(const float4*)&WaS_s[j << 2];  // broadcast
                float4 v = *(const float4*)&va_s[j << 2];   // broadcast
                a0 += tanhapx(u.x + w.x) * v.x + tanhapx(u.y + w.y) * v.y;
                a1 += tanhapx(u.z + w.z) * v.z + tanhapx(u.w + w.w) * v.w;
            }
            float s = a0 + a1;
            const uint32_t doff = (uint32_t)(SPART_OFF + buf * (CPG * TT) + crk * TT + tid) * 4u;
            const uint32_t boff = (uint32_t)(BAR_OFF * 4 + buf * 8);
            #pragma unroll
            for (int r = 0; r < CPG; r++)
                st_async(rbase[r] + doff, s, rbase[r] + boff);
        } else {
            // -------- warps 4-7: S/P from received sig (true shadow) --------
            const int o = (tid - 128) << 2;                // 0..508, step 4
            float4 sg4 = *(const float4*)&sgc[(o >> 6) * SG_PITCH + (o & 63)];
            float4 ew4 = *(const float4*)&ew_s[o];
            float e0 = __fdividef(sg4.x, 1.f - sg4.x);
            float e1 = __fdividef(sg4.y, 1.f - sg4.y);
            float e2 = __fdividef(sg4.z, 1.f - sg4.z);
            float e3 = __fdividef(sg4.w, 1.f - sg4.w);
            float ps = (e0 + e1) + (e2 + e3);
            float pd = (e0 * ew4.x + e1 * ew4.y) + (e2 * ew4.z + e3 * ew4.w);
            ps = wredsum(ps);
            pd = wredsum(pd);
            if (lane == 0) { red[8 + (wid - 4)] = ps; red[12 + (wid - 4)] = pd; }
        }

        // -------- wait for all score partials --------
        const uint32_t scorebar_l = barbase + buf * 8;
        mbar_wait(scorebar_l, (t >> 1) & 1);
        if (tid == 0) mbar_arm(scorebar_l, TX_SCORE);

        // -------- P3: softmax over T --------
        const float* sp = sm + SPART_OFF + buf * (CPG * TT);
        if (tid < TT) {
            float c0 = 0.f, c1 = 0.f;
            #pragma unroll
            for (int r = 0; r < 8; r += 2) {
                c0 += sp[(r << 7) + tid];
                c1 += sp[((r + 1) << 7) + tid];
            }
            float esv = __expf(c0 + c1);                   // |score| small: no max-sub
            wbuf[tid] = esv;
            float spp = wredsum(esv);
            if (lane == 0) red[wid] = spp;                 // wid 0..3
        }
        __syncthreads();                                   // s3: wbuf + red(esum,S,P)
        const float esum = (red[0] + red[1]) + (red[2] + red[3]);

        // ctx partial: thread (oc,kc) covers t' in [kc*32, kc*32+32)
        {
            float c0 = 0.f, c1 = 0.f;
            const int base = kc << 5;
            #pragma unroll
            for (int j = 0; j < 8; j++) {
                float4 wb = *(const float4*)&wbuf[base + (j << 2)];
                c0 += wb.x * IC_s[((base + (j << 2) + 0) << 6) + oc]
                    + wb.y * IC_s[((base + (j << 2) + 1) << 6) + oc];
                c1 += wb.z * IC_s[((base + (j << 2) + 2) << 6) + oc]
                    + wb.w * IC_s[((base + (j << 2) + 3) << 6) + oc];
            }
            partB[tid] = c0 + c1;
        }
        __syncthreads();                                   // s4
        if (tid < OSL) {
            const float S = (red[8]  + red[9])  + (red[10] + red[11]);
            const float P = (red[12] + red[13]) + (red[14] + red[15]);
            const float woy = __fdividef(P, S);
            float ctx  = (partB[tid] + partB[64 + tid]) + (partB[128 + tid] + partB[192 + tid]);
            float pred = woy + xo + __fdividef(ctx, esum) + bo_r;

            // ship sig FIRST (inter-step critical path), then store out
            float sg = __fdividef(1.f, 1.f + __expf(-pred));
            if (t < TT - 1) {
                const uint32_t sgoff =
                    (uint32_t)(SG_OFF + buf * (CPG * SG_PITCH) + crk * SG_PITCH + tid) * 4u;
                const uint32_t sboff = (uint32_t)(BAR_OFF * 4 + 16 + buf * 8);
                #pragma unroll
                for (int r = 0; r < CPG; r++)
                    st_async(rbase[r] + sgoff, sg, rbase[r] + sboff);
            }
            out[(size_t)(b * TT + t) * OO + o_base + tid] = pred;
        }
    }
    CLUSTER_SYNC();   // no CTA exits while peers' in-flight stores may target it
}

// =======================================================================
// launch
// =======================================================================
extern "C" void kernel_launch(void* const* d_in, const int* in_sizes, int n_in,
                              void* d_out, int out_size)
{
    const float* inputs = (const float*)d_in[0];
    const float* Wa     = (const float*)d_in[1];
    const float* Ua     = (const float*)d_in[2];
    const float* Va     = (const float*)d_in[3];
    const float* Ba     = (const float*)d_in[4];
    const float* Wo     = (const float*)d_in[5];
    const float* Uo     = (const float*)d_in[6];
    const float* Co     = (const float*)d_in[7];
    const float* Bo     = (const float*)d_in[8];
    const float* emb    = (const float*)d_in[9];
    float* out = (float*)d_out;

    dim3 g(16, 8, 3);
    gemm3_kernel<<<g, 256>>>(inputs, Ua, Co, Uo, Ba);
    embwo_kernel<<<64, 256>>>(emb, Wo);

    cudaFuncSetAttribute(scan_kernel,
                         cudaFuncAttributeMaxDynamicSharedMemorySize, SMEM_BYTES);
    scan_kernel<<<BB * CPG, NTH, SMEM_BYTES>>>(Wa, Va, Bo, out);
}

// round 17
// speedup vs baseline: 1.0911x; 1.0761x over previous
#include <cuda_runtime.h>
#include <cuda_bf16.h>
#include <cstdint>

#define BB 8
#define TT 128
#define DD 512
#define OO 512
#define CPG 8              // CTAs per cluster (one cluster per batch)
#define OSL (OO/CPG)       // 64  output-col slice per CTA
#define NTH 256
#define FULLMASK 0xffffffffu

// ---------------- device scratch (no allocations allowed) ----------------
__device__ float g_UaH[BB*TT*OO];   // inputs@Ua + Ba
__device__ float g_IC [BB*TT*OO];   // inputs@Co
__device__ float g_XUo[BB*TT*OO];   // inputs@Uo
__device__ float g_embWo[OO];       // emb@Wo
// bf16-split operands for the tensor-core GEMM
__device__ __nv_bfloat16 g_Ahi[BB*TT*DD];      // inputs hi
__device__ __nv_bfloat16 g_Alo[BB*TT*DD];      // inputs lo
__device__ __nv_bfloat16 g_Bthi[3*DD*OO];      // B^T hi  ([z][n][k])
__device__ __nv_bfloat16 g_Btlo[3*DD*OO];      // B^T lo

// ---------------- helpers ----------------
__device__ __forceinline__ float wredsum(float v) {
    #pragma unroll
    for (int s = 16; s; s >>= 1) v += __shfl_xor_sync(FULLMASK, v, s);
    return v;
}
__device__ __forceinline__ float tanhapx(float x) {
    float y;
    asm("tanh.approx.f32 %0, %1;" : "=f"(y) : "f"(x));
    return y;
}
__device__ __forceinline__ uint32_t smem_u32(const void* p) {
    uint32_t a;
    asm("{ .reg .u64 t; cvta.to.shared.u64 t, %1; cvt.u32.u64 %0, t; }"
        : "=r"(a) : "l"(p));
    return a;
}
__device__ __forceinline__ uint32_t dsm_map(uint32_t laddr, uint32_t rank) {
    uint32_t r;
    asm("mapa.shared::cluster.u32 %0, %1, %2;" : "=r"(r) : "r"(laddr), "r"(rank));
    return r;
}
__device__ __forceinline__ void mbar_init(uint32_t a, uint32_t cnt) {
    asm volatile("mbarrier.init.shared.b64 [%0], %1;" :: "r"(a), "r"(cnt) : "memory");
}
__device__ __forceinline__ void mbar_arm(uint32_t a, uint32_t tx) {
    asm volatile("mbarrier.arrive.expect_tx.shared.b64 _, [%0], %1;"
                 :: "r"(a), "r"(tx) : "memory");
}
__device__ __forceinline__ void mbar_wait(uint32_t a, uint32_t parity) {
    asm volatile(
        "{\n\t.reg .pred P;\n\t"
        "W_%=:\n\t"
        "mbarrier.try_wait.parity.acquire.cluster.shared::cta.b64 P, [%0], %1, 0x989680;\n\t"
        "@!P bra W_%=;\n\t}"
        :: "r"(a), "r"(parity) : "memory");
}
__device__ __forceinline__ void st_async(uint32_t raddr, float v, uint32_t rbar) {
    asm volatile(
        "st.async.shared::cluster.mbarrier::complete_tx::bytes.b32 [%0], %1, [%2];"
        :: "r"(raddr), "r"(__float_as_uint(v)), "r"(rbar) : "memory");
}
#define CLUSTER_SYNC() do { \
    asm volatile("barrier.cluster.arrive.aligned;" ::: "memory"); \
    asm volatile("barrier.cluster.wait.aligned;"   ::: "memory"); \
} while (0)

__device__ __forceinline__ void fma2(unsigned long long& d,
                                     unsigned long long a, unsigned long long b) {
    asm("fma.rn.f32x2 %0, %1, %2, %0;" : "+l"(d) : "l"(a), "l"(b));
}
__device__ __forceinline__ unsigned long long pack2(float x, float y) {
    unsigned long long r;
    asm("mov.b64 %0, {%1, %2};" : "=l"(r) : "f"(x), "f"(y));
    return r;
}
__device__ __forceinline__ float2 unpack2(unsigned long long v) {
    float2 r;
    asm("mov.b64 {%0, %1}, %2;" : "=f"(r.x), "=f"(r.y) : "l"(v));
    return r;
}

// ---------------- mma.sync / ldmatrix (sm_80+ PTX, NOT arch-specific) ----------------
#define LDSM4(r, addr) \
    asm volatile("ldmatrix.sync.aligned.m8n8.x4.shared.b16 {%0,%1,%2,%3}, [%4];" \
        : "=r"((r)[0]), "=r"((r)[1]), "=r"((r)[2]), "=r"((r)[3]) : "r"(addr))

#define MMA_BF16(d, a, b) \
    asm volatile("mma.sync.aligned.m16n8k16.row.col.f32.bf16.bf16.f32 " \
        "{%0,%1,%2,%3}, {%4,%5,%6,%7}, {%8,%9}, {%0,%1,%2,%3};" \
        : "+f"((d)[0]), "+f"((d)[1]), "+f"((d)[2]), "+f"((d)[3]) \
        : "r"((a)[0]), "r"((a)[1]), "r"((a)[2]), "r"((a)[3]), \
          "r"((b)[0]), "r"((b)[1]))

// =======================================================================
// conversion kernels: fp32 -> (hi, lo) bf16 split
// =======================================================================
__global__ __launch_bounds__(256) void convA_kernel(const float* __restrict__ A)
{
    int i = blockIdx.x * 256 + threadIdx.x;        // 524288 total
    float x = A[i];
    __nv_bfloat16 h = __float2bfloat16(x);
    g_Ahi[i] = h;
    g_Alo[i] = __float2bfloat16(x - __bfloat162float(h));
}

// transpose + split: Bt[z][n][k] = B_z[k][n]
__global__ __launch_bounds__(256) void convB_kernel(
    const float* __restrict__ Ua, const float* __restrict__ Co,
    const float* __restrict__ Uo)
{
    __shared__ float tile[32][33];
    const float* B = (blockIdx.z == 0) ? Ua : ((blockIdx.z == 1) ? Co : Uo);
    const int n0 = blockIdx.x << 5;
    const int k0 = blockIdx.y << 5;
    const int tx = threadIdx.x & 31;
    const int ty = threadIdx.x >> 5;               // 0..7
    for (int r = ty; r < 32; r += 8)
        tile[r][tx] = B[(size_t)(k0 + r) * OO + n0 + tx];
    __syncthreads();
    const size_t zb = (size_t)blockIdx.z * DD * OO;
    for (int r = ty; r < 32; r += 8) {
        float x = tile[tx][r];                     // B[k0+tx][n0+r]
        __nv_bfloat16 h = __float2bfloat16(x);
        size_t o = zb + (size_t)(n0 + r) * DD + k0 + tx;
        g_Bthi[o] = h;
        g_Btlo[o] = __float2bfloat16(x - __bfloat162float(h));
    }
}

// =======================================================================
// mma.sync GEMM: C_z[1024x512] = A @ B_z via bf16 split (3 terms,
// fp32 accum): C = Ahi*Bhi + Ahi*Blo + Alo*Bhi.
// CTA tile 128x128, 8 warps (2m x 4n), warp tile 64x32, BK=64.
// Smem pitch 72 bf16 (144B) -> LDSM conflict-free. grid (8,4,3).
// =======================================================================
#define GM_BK    64
#define GM_PITCH 72                         // bf16 per smem row
#define GS_MAT   (128*GM_PITCH*2)           // 18432 B per matrix
#define GS_AHI   0
#define GS_ALO   (1*GS_MAT)
#define GS_BHI   (2*GS_MAT)
#define GS_BLO   (3*GS_MAT)
#define GS_TOTAL (4*GS_MAT)                 // 73728 B

__global__ __launch_bounds__(256) void mma_gemm_kernel(const float* __restrict__ Ba)
{
    extern __shared__ char smc[];
    const uint32_t sb = smem_u32(smc);
    const int tid  = threadIdx.x;
    const int lane = tid & 31;
    const int wid  = tid >> 5;
    const int wm   = wid & 1;            // 0..1  (m offset wm*64)
    const int wn   = wid >> 1;           // 0..3  (n offset wn*32)
    const int m0   = blockIdx.x << 7;
    const int n0   = blockIdx.y << 7;
    const int z    = blockIdx.z;
    const __nv_bfloat16* Bh = g_Bthi + (size_t)z * DD * OO;
    const __nv_bfloat16* Bl = g_Btlo + (size_t)z * DD * OO;
    float* Cout = (z == 0) ? g_UaH : ((z == 1) ? g_IC : g_XUo);

    float d[4][4][4];                    // [mi][ni][frag]
    #pragma unroll
    for (int mi = 0; mi < 4; mi++)
        #pragma unroll
        for (int ni = 0; ni < 4; ni++)
            #pragma unroll
            for (int j = 0; j < 4; j++) d[mi][ni][j] = 0.f;

    // LDSM lane addressing (x4, non-trans):
    //   A mats: 0:(m0-7,k0-7) 1:(m8-15,k0-7) 2:(m0-7,k8-15) 3:(m8-15,k8-15)
    //   B mats: 0:(n0-7,k0-7) 1:(n0-7,k8-15) 2:(n8-15,k0-7) 3:(n8-15,k8-15)
    const int a_r = (lane & 7) + ((lane >> 3) & 1) * 8;
    const int a_k = (lane >> 4) * 8;
    const int b_r = (lane & 7) + ((lane >> 4) & 1) * 8;
    const int b_k = ((lane >> 3) & 1) * 8;

    const uint32_t aHi = sb + GS_AHI + (uint32_t)((wm * 64 + a_r) * GM_PITCH + a_k) * 2;
    const uint32_t aLo = aHi + (GS_ALO - GS_AHI);
    const uint32_t bHi = sb + GS_BHI + (uint32_t)((wn * 32 + b_r) * GM_PITCH + b_k) * 2;
    const uint32_t bLo = bHi + (GS_BLO - GS_BHI);

    for (int c = 0; c < DD / GM_BK; c++) {
        const int kc0 = c * GM_BK;
        __syncthreads();                          // previous compute done
        for (int i = tid; i < 1024; i += 256) {   // 128 rows x 8 uint4
            const int row = i >> 3, g = i & 7;
            const uint32_t so = (uint32_t)(row * GM_PITCH * 2 + g * 16);
            const size_t ao = (size_t)(m0 + row) * DD + kc0 + g * 8;
            const size_t bo = (size_t)(n0 + row) * DD + kc0 + g * 8;
            *(uint4*)(smc + GS_AHI + so) = *(const uint4*)(g_Ahi + ao);
            *(uint4*)(smc + GS_ALO + so) = *(const uint4*)(g_Alo + ao);
            *(uint4*)(smc + GS_BHI + so) = *(const uint4*)(Bh + bo);
            *(uint4*)(smc + GS_BLO + so) = *(const uint4*)(Bl + bo);
        }
        __syncthreads();
        #pragma unroll
        for (int ks = 0; ks < GM_BK / 16; ks++) {
            const uint32_t ko = (uint32_t)(ks * 32);       // 16 bf16 = 32 B
            uint32_t ah[4][4], al[4][4];
            #pragma unroll
            for (int mi = 0; mi < 4; mi++) {
                const uint32_t off = (uint32_t)(mi * 16 * GM_PITCH * 2) + ko;
                LDSM4(ah[mi], aHi + off);
                LDSM4(al[mi], aLo + off);
            }
            uint32_t bh[2][4], bl[2][4];   // pair p: regs[0,1]=sub(2p), [2,3]=sub(2p+1)
            #pragma unroll
            for (int p = 0; p < 2; p++) {
                const uint32_t off = (uint32_t)(p * 16 * GM_PITCH * 2) + ko;
                LDSM4(bh[p], bHi + off);
                LDSM4(bl[p], bLo + off);
            }
            #pragma unroll
            for (int mi = 0; mi < 4; mi++)
                #pragma unroll
                for (int ni = 0; ni < 4; ni++) {
                    uint32_t* bhp = &bh[ni >> 1][(ni & 1) * 2];
                    uint32_t* blp = &bl[ni >> 1][(ni & 1) * 2];
                    MMA_BF16(d[mi][ni], ah[mi], bhp);
                    MMA_BF16(d[mi][ni], ah[mi], blp);
                    MMA_BF16(d[mi][ni], al[mi], bhp);
                }
        }
    }

    // epilogue: c-fragment -> global (+Ba for z==0)
    const int g  = lane >> 2;
    const int tg = lane & 3;
    #pragma unroll
    for (int mi = 0; mi < 4; mi++) {
        const int r0 = m0 + wm * 64 + mi * 16 + g;
        #pragma unroll
        for (int ni = 0; ni < 4; ni++) {
            const int col = n0 + wn * 32 + ni * 8 + tg * 2;
            float add0 = 0.f, add1 = 0.f;
            if (z == 0) { add0 = Ba[col]; add1 = Ba[col + 1]; }
            *(float2*)&Cout[(size_t)r0 * OO + col] =
                make_float2(d[mi][ni][0] + add0, d[mi][ni][1] + add1);
            *(float2*)&Cout[(size_t)(r0 + 8) * OO + col] =
                make_float2(d[mi][ni][2] + add0, d[mi][ni][3] + add1);
        }
    }
}

// =======================================================================
// embWo[i] = sum_j emb[i][j] * Wo[j]
// =======================================================================
__global__ __launch_bounds__(256) void embwo_kernel(
    const float* __restrict__ emb, const float* __restrict__ Wo)
{
    const int row  = (blockIdx.x << 3) + (threadIdx.x >> 5);
    const int lane = threadIdx.x & 31;
    const float* rp = emb + row * OO;
    float acc = 0.f;
    #pragma unroll 4
    for (int j = lane; j < OO; j += 32) acc += rp[j] * Wo[j];
    acc = wredsum(acc);
    if (lane == 0) g_embWo[row] = acc;
}

// =======================================================================
// Persistent clustered scan — R9 best (289.1us), verbatim.
// =======================================================================
#define UAH_PITCH 76
#define SG_PITCH  68        // 64 sig + 4 scalar slots per rank
#define UAH_OFF   0                              // [128][76] = 9728
#define IC_OFF    (UAH_OFF + TT*UAH_PITCH)       // [128][64] = 8192
#define SG_OFF    (IC_OFF + TT*OSL)              // 2 x [8][68] = 1088
#define SPART_OFF (SG_OFF + 2*CPG*SG_PITCH)      // 2 x [8][128] = 2048
#define WAS_OFF   (SPART_OFF + 2*CPG*TT)         // [64]
#define WBUF_OFF  (WAS_OFF + OSL)                // [128]
#define RED_OFF   (WBUF_OFF + TT)                // [32]
#define PARTA_OFF (RED_OFF + 32)                 // [256]
#define PARTB_OFF (PARTA_OFF + 256)              // [256]
#define BAR_OFF   (PARTB_OFF + 256)              // 4 x u64
#define SMEM_FLOATS (BAR_OFF + 8)
#define SMEM_BYTES  (SMEM_FLOATS * 4)

#define TX_SCORE (CPG*TT*4)          // 4096 bytes/phase
#define TX_SIG   (CPG*(OSL+4)*4)     // 2176 bytes/phase

__global__ __launch_bounds__(NTH, 1) __cluster_dims__(CPG, 1, 1)
void scan_kernel(const float* __restrict__ Wa,
                 const float* __restrict__ Va,
                 const float* __restrict__ Bo,
                 float* __restrict__ out)
{
    extern __shared__ float sm[];
    float* UaH_s = sm + UAH_OFF;
    float* IC_s  = sm + IC_OFF;
    float* wbuf  = sm + WBUF_OFF;
    float* WaS_s = sm + WAS_OFF;
    float* red   = sm + RED_OFF;
    float* partA = sm + PARTA_OFF;
    float* partB = sm + PARTB_OFF;

    const uint32_t sbase   = smem_u32(sm);
    const uint32_t barbase = sbase + BAR_OFF * 4;

    const int tid  = threadIdx.x;
    const int lane = tid & 31;
    const int wid  = tid >> 5;
    const int b    = blockIdx.x >> 3;     // batch
    const int crk  = blockIdx.x & 7;      // cluster rank
    const int o_base = crk * OSL;
    const int oc = tid & 63;
    const int kc = tid >> 6;              // 0..3
    const int ts = tid & 127;
    const int q  = tid >> 7;              // 0..1

    // ---------------- prologue ----------------
    for (int i = tid; i < TT * OSL; i += NTH) {
        int tt = i >> 6, o = i & 63;
        UaH_s[tt * UAH_PITCH + o] = g_UaH[(size_t)(b * TT + tt) * OO + o_base + o];
        IC_s[(tt << 6) + o]       = g_IC [(size_t)(b * TT + tt) * OO + o_base + o];
    }

    unsigned long long wreg2[64];
    {
        const int col = o_base + oc;
        #pragma unroll
        for (int j = 0; j < 64; j++) {
            float w0 = Wa[(size_t)(kc * 128 + 2 * j)     * OO + col];
            float w1 = Wa[(size_t)(kc * 128 + 2 * j + 1) * OO + col];
            wreg2[j] = pack2(w0, w1);
        }
    }
    float va_r[32];
    #pragma unroll
    for (int j = 0; j < 32; j++) va_r[j] = Va[o_base + (q << 5) + j];

    const float ew0   = g_embWo[tid];
    const float ew1   = g_embWo[tid + 256];
    const float ew_sl = g_embWo[o_base + oc];
    const float bo_r  = (tid < OSL) ? Bo[o_base + tid] : 0.f;

    uint32_t rbase[CPG];
    #pragma unroll
    for (int r = 0; r < CPG; r++) rbase[r] = dsm_map(sbase, r);

    if (tid == 0) {
        #pragma unroll
        for (int i = 0; i < 4; i++) mbar_init(barbase + i * 8, 1);
        mbar_arm(barbase + 0,  TX_SCORE);
        mbar_arm(barbase + 8,  TX_SCORE);
        mbar_arm(barbase + 16, TX_SIG);
        mbar_arm(barbase + 24, TX_SIG);
    }

    // t=0 seed: sig(-1)=0.5, S=512, P=sum(embWo) in sg buffer 1
    float p0p = wredsum(ew0 + ew1);
    if (lane == 0) red[wid] = p0p;
    {
        float* sg1 = sm + SG_OFF + CPG * SG_PITCH;
        for (int i = tid; i < CPG * SG_PITCH; i += NTH)
            sg1[i] = ((i % SG_PITCH) < OSL) ? 0.5f : 0.f;
    }
    __syncthreads();
    if (tid == 0) {
        float P0 = 0.f;
        #pragma unroll
        for (int i = 0; i < 8; i++) P0 += red[i];
        float* sg1 = sm + SG_OFF + CPG * SG_PITCH;
        sg1[OSL + 0] = 512.f;
        sg1[OSL + 2] = P0;
    }
    __syncthreads();
    CLUSTER_SYNC();

    // ---------------- scan over T steps ----------------
    for (int t = 0; t < TT; t++) {
        const int buf = t & 1;

        float xo = 0.f;
        if (tid < OSL)
            xo = __ldg(&g_XUo[(size_t)(b * TT + ((t + TT - 1) & (TT - 1))) * OO + o_base + tid]);

        const uint32_t sigbar_l = barbase + 16 + (buf ^ 1) * 8;
        if (t > 0) {
            mbar_wait(sigbar_l, ((t - 1) >> 1) & 1);
            if (tid == 0) mbar_arm(sigbar_l, TX_SIG);
        }
        const float* sgc = sm + SG_OFF + (buf ^ 1) * (CPG * SG_PITCH);

        float S = 0.f, P = 0.f;
        #pragma unroll
        for (int r = 0; r < CPG; r++) {
            const float* sr = sgc + r * SG_PITCH + OSL;
            S += sr[0] + sr[1];
            P += sr[2] + sr[3];
        }
        const float woy = __fdividef(P, S);

        {
            unsigned long long acc2 = 0ull;
            #pragma unroll
            for (int rr = 0; rr < 2; rr++) {
                const ulonglong2* sp2 =
                    (const ulonglong2*)(sgc + (2 * kc + rr) * SG_PITCH);
                #pragma unroll
                for (int i = 0; i < 16; i++) {
                    ulonglong2 sv = sp2[i];
                    fma2(acc2, sv.x, wreg2[rr * 32 + 2 * i]);
                    fma2(acc2, sv.y, wreg2[rr * 32 + 2 * i + 1]);
                }
            }
            float2 f = unpack2(acc2);
            partA[tid] = f.x + f.y;
        }
        __syncthreads();
        if (tid < OSL)
            WaS_s[tid] = partA[tid] + partA[64 + tid] + partA[128 + tid] + partA[192 + tid];
        __syncthreads();

        {
            const float* urow = UaH_s + ts * UAH_PITCH + (q << 5);
            const float* wp   = WaS_s + (q << 5);
            float acc = 0.f;
            #pragma unroll
            for (int j = 0; j < 8; j++) {
                float4 u = *(const float4*)&urow[j << 2];
                float4 w = *(const float4*)&wp[j << 2];
                acc += tanhapx(u.x + w.x) * va_r[(j << 2) + 0]
                     + tanhapx(u.y + w.y) * va_r[(j << 2) + 1]
                     + tanhapx(u.z + w.z) * va_r[(j << 2) + 2]
                     + tanhapx(u.w + w.w) * va_r[(j << 2) + 3];
            }
            partB[(q << 7) + ts] = acc;
        }
        __syncthreads();
        if (tid < TT) {
            float s = partB[tid] + partB[128 + tid];
            const uint32_t doff = (uint32_t)(SPART_OFF + buf * (CPG * TT) + crk * TT + tid) * 4u;
            const uint32_t boff = (uint32_t)(BAR_OFF * 4 + buf * 8);
            #pragma unroll
            for (int r = 0; r < CPG; r++)
                st_async(rbase[r] + doff, s, rbase[r] + boff);
        }

        const uint32_t scorebar_l = barbase + buf * 8;
        mbar_wait(scorebar_l, (t >> 1) & 1);
        if (tid == 0) mbar_arm(scorebar_l, TX_SCORE);

        const float* sp = sm + SPART_OFF + buf * (CPG * TT);
        if (tid < TT) {
            float c0 = 0.f, c1 = 0.f;
            #pragma unroll
            for (int r = 0; r < 8; r += 2) {
                c0 += sp[(r << 7) + tid];
                c1 += sp[((r + 1) << 7) + tid];
            }
            float esv = __expf(c0 + c1);
            wbuf[tid] = esv;
            float spp = wredsum(esv);
            if (lane == 0) red[16 + wid] = spp;
        }
        __syncthreads();
        const float esum = (red[16] + red[17]) + (red[18] + red[19]);

        {
            float c0 = 0.f, c1 = 0.f;
            const int base = kc << 5;
            #pragma unroll
            for (int j = 0; j < 8; j++) {
                float4 wb = *(const float4*)&wbuf[base + (j << 2)];
                c0 += wb.x * IC_s[((base + (j << 2) + 0) << 6) + oc]
                    + wb.y * IC_s[((base + (j << 2) + 1) << 6) + oc];
                c1 += wb.z * IC_s[((base + (j << 2) + 2) << 6) + oc]
                    + wb.w * IC_s[((base + (j << 2) + 3) << 6) + oc];
            }
            partB[tid] = c0 + c1;
        }
        __syncthreads();
        if (tid < OSL) {
            float ctx  = (partB[tid] + partB[64 + tid]) + (partB[128 + tid] + partB[192 + tid]);
            float pred = woy + xo + __fdividef(ctx, esum) + bo_r;

            float e  = __expf(pred);
            float sg = __fdividef(1.f, 1.f + __expf(-pred));
            float pe = wredsum(e);
            float pp = wredsum(e * ew_sl);
            if (t < TT - 1) {
                const uint32_t sgoff =
                    (uint32_t)(SG_OFF + buf * (CPG * SG_PITCH) + crk * SG_PITCH + tid) * 4u;
                const uint32_t sboff = (uint32_t)(BAR_OFF * 4 + 16 + buf * 8);
                #pragma unroll
                for (int r = 0; r < CPG; r++)
                    st_async(rbase[r] + sgoff, sg, rbase[r] + sboff);
                if (lane == 0) {
                    const int w = tid >> 5;
                    const uint32_t so =
                        (uint32_t)(SG_OFF + buf * (CPG * SG_PITCH) + crk * SG_PITCH + OSL + w) * 4u;
                    const uint32_t po = so + 8u;
                    #pragma unroll
                    for (int r = 0; r < CPG; r++) {
                        st_async(rbase[r] + so, pe, rbase[r] + sboff);
                        st_async(rbase[r] + po, pp, rbase[r] + sboff);
                    }
                }
            }
            out[(size_t)(b * TT + t) * OO + o_base + tid] = pred;
        }
    }
    CLUSTER_SYNC();
}

// =======================================================================
// launch
// =======================================================================
extern "C" void kernel_launch(void* const* d_in, const int* in_sizes, int n_in,
                              void* d_out, int out_size)
{
    const float* inputs = (const float*)d_in[0];
    const float* Wa     = (const float*)d_in[1];
    const float* Ua     = (const float*)d_in[2];
    const float* Va     = (const float*)d_in[3];
    const float* Ba     = (const float*)d_in[4];
    const float* Wo     = (const float*)d_in[5];
    const float* Uo     = (const float*)d_in[6];
    const float* Co     = (const float*)d_in[7];
    const float* Bo     = (const float*)d_in[8];
    const float* emb    = (const float*)d_in[9];
    float* out = (float*)d_out;

    convA_kernel<<<(BB*TT*DD)/256, 256>>>(inputs);
    convB_kernel<<<dim3(16, 16, 3), 256>>>(Ua, Co, Uo);
    embwo_kernel<<<64, 256>>>(emb, Wo);

    cudaFuncSetAttribute(mma_gemm_kernel,
                         cudaFuncAttributeMaxDynamicSharedMemorySize, GS_TOTAL);
    mma_gemm_kernel<<<dim3(8, 4, 3), 256, GS_TOTAL>>>(Ba);

    cudaFuncSetAttribute(scan_kernel,
                         cudaFuncAttributeMaxDynamicSharedMemorySize, SMEM_BYTES);
    scan_kernel<<<BB * CPG, NTH, SMEM_BYTES>>>(Wa, Va, Bo, out);
}